// round 1
// baseline (speedup 1.0000x reference)
#include <cuda_runtime.h>

// ---------------------------------------------------------------------------
// QuantumLayer: out[r] = <psi_r| U† Z5 U |psi_r>, psi_r = x_r / ||x_r||.
// Lightcone of Z5 through the circuit touches only qubits {3,4,5} (the top 3
// bits of the 64-dim index). So M = O (8x8, Hermitian) ⊗ I_8 and
//   out = ( Σ_{a,b} ReO[a][b] * dot(x[8a..], x[8b..]) ) / ||x||^2
// Kernel A builds ReO (8x8) from params on device; kernel B does the
// memory-bound per-row Gram quadratic form.
// ---------------------------------------------------------------------------

__device__ float g_C[64];   // ReO, row-major 8x8

struct c2 { float x, y; };
__device__ __forceinline__ c2 cmul(c2 a, c2 b) { return { a.x*b.x - a.y*b.y, a.x*b.y + a.y*b.x }; }
__device__ __forceinline__ c2 cadd(c2 a, c2 b) { return { a.x + b.x, a.y + b.y }; }

struct U2 { c2 m00, m01, m10, m11; };

// qiskit U(theta, phi, lam)
__device__ __forceinline__ U2 u3(float th, float ph, float la) {
    float s, c;   sincosf(0.5f * th, &s, &c);
    float sph, cph; sincosf(ph, &sph, &cph);
    float sla, cla; sincosf(la, &sla, &cla);
    float spl, cpl; sincosf(ph + la, &spl, &cpl);
    U2 u;
    u.m00 = {  c,        0.f     };
    u.m01 = { -cla * s, -sla * s };
    u.m10 = {  cph * s,  sph * s };
    u.m11 = {  cpl * c,  spl * c };
    return u;
}

template <int BIT>
__device__ __forceinline__ void apply1(c2 (&w)[8], U2 u) {
#pragma unroll
    for (int a = 0; a < 8; a++) {
        if (!(a & BIT)) {
            c2 t0 = w[a], t1 = w[a | BIT];
            w[a]       = cadd(cmul(u.m00, t0), cmul(u.m01, t1));
            w[a | BIT] = cadd(cmul(u.m10, t0), cmul(u.m11, t1));
        }
    }
}

// Build ReO. 3-qubit index a: bit0 = qubit3, bit1 = qubit4, bit2 = qubit5.
// Sub-circuit (forward order): U3(q3;9), U3(q4;12), U3(q5;15), CX(4->3),
// P(19;q3), U3(q3;26), U3(q5;29), CU(35;3->5). Then O = W† diag(z) W with
// z_a = +1 if (a&4)==0 else -1.
__global__ void build_obs_kernel(const float* __restrict__ p) {
    __shared__ float Wr[8][8];
    __shared__ float Wi[8][8];
    int t = threadIdx.x;

    if (t < 8) {
        c2 w[8];
#pragma unroll
        for (int a = 0; a < 8; a++) w[a] = { (a == t) ? 1.f : 0.f, 0.f };

        apply1<1>(w, u3(p[9],  p[10], p[11]));   // layer1 q3
        apply1<2>(w, u3(p[12], p[13], p[14]));   // layer1 q4
        apply1<4>(w, u3(p[15], p[16], p[17]));   // layer1 q5

        // CX control q4 (bit1) -> target q3 (bit0)
#pragma unroll
        for (int a = 0; a < 8; a++) {
            if ((a & 2) && !(a & 1)) { c2 tmp = w[a]; w[a] = w[a | 1]; w[a | 1] = tmp; }
        }

        // P(params[19]) on q3 (bit0)
        {
            float sp, cp; sincosf(p[19], &sp, &cp);
            c2 e = { cp, sp };
#pragma unroll
            for (int a = 0; a < 8; a++) if (a & 1) w[a] = cmul(w[a], e);
        }

        apply1<1>(w, u3(p[26], p[27], p[28]));   // layer2 q3
        apply1<4>(w, u3(p[29], p[30], p[31]));   // layer2 q5

        // CU(params 35..37): control q3 (bit0) -> target q5 (bit2)
        {
            U2 u = u3(p[35], p[36], p[37]);
#pragma unroll
            for (int a = 0; a < 8; a++) {
                if ((a & 1) && !(a & 4)) {
                    c2 t0 = w[a], t1 = w[a | 4];
                    w[a]     = cadd(cmul(u.m00, t0), cmul(u.m01, t1));
                    w[a | 4] = cadd(cmul(u.m10, t0), cmul(u.m11, t1));
                }
            }
        }

#pragma unroll
        for (int a = 0; a < 8; a++) { Wr[a][t] = w[a].x; Wi[a][t] = w[a].y; }
    }
    __syncthreads();

    if (t < 64) {
        int a = t >> 3, b = t & 7;
        float acc = 0.f;
#pragma unroll
        for (int c = 0; c < 8; c++) {
            float z = (c & 4) ? -1.f : 1.f;
            acc += z * (Wr[c][a] * Wr[c][b] + Wi[c][a] * Wi[c][b]);
        }
        g_C[t] = acc;
    }
}

// Per-row quadratic form. One thread per row: 16x LDG.128, Gram of the 8
// contiguous 8-element blocks against ReO, normalized by ||x||^2.
__global__ void __launch_bounds__(256) quadform_kernel(
    const float* __restrict__ feat, float* __restrict__ out, int n) {
    __shared__ float C[64];
    int tid = threadIdx.x;
    if (tid < 64) {
        int a = tid >> 3, b = tid & 7;
        float v = g_C[tid];
        C[tid] = (a == b) ? v : 2.f * v;   // off-diagonals counted twice
    }
    __syncthreads();

    int row = blockIdx.x * 256 + tid;
    if (row >= n) return;

    float x[64];
    const float4* pv = reinterpret_cast<const float4*>(feat) + (size_t)row * 16;
#pragma unroll
    for (int i = 0; i < 16; i++) {
        float4 v = __ldg(pv + i);
        x[4*i + 0] = v.x; x[4*i + 1] = v.y; x[4*i + 2] = v.z; x[4*i + 3] = v.w;
    }

    float Q = 0.f, N = 0.f;
#pragma unroll
    for (int a = 0; a < 8; a++) {
#pragma unroll
        for (int b = a; b < 8; b++) {
            float s = 0.f;
#pragma unroll
            for (int k = 0; k < 8; k++) s += x[8*a + k] * x[8*b + k];
            Q += C[8*a + b] * s;
            if (a == b) N += s;
        }
    }

    // jnp.isclose(norm, 0) with atol=1e-8  ->  N = norm^2 <= 1e-16 -> psi = e0
    out[row] = (N <= 1e-16f) ? C[0] : (Q / N);
}

extern "C" void kernel_launch(void* const* d_in, const int* in_sizes, int n_in,
                              void* d_out, int out_size) {
    // metadata order: features (B*64 floats), params (54 floats). Be defensive
    // about ordering by size.
    int fi = 0, pi = 1;
    if (n_in >= 2 && in_sizes[0] == 54) { fi = 1; pi = 0; }

    const float* feat   = (const float*)d_in[fi];
    const float* params = (const float*)d_in[pi];
    float* out = (float*)d_out;

    int n = in_sizes[fi] / 64;

    build_obs_kernel<<<1, 64>>>(params);
    int grid = (n + 255) / 256;
    quadform_kernel<<<grid, 256>>>(feat, out, n);
}

// round 2
// speedup vs baseline: 1.4290x; 1.4290x over previous
#include <cuda_runtime.h>

// ---------------------------------------------------------------------------
// QuantumLayer: out[r] = <psi_r| U† Z5 U |psi_r>, psi_r = x_r / ||x_r||.
// Lightcone of Z5 touches only qubits {3,4,5} (top 3 index bits), so
// M = O (8x8 Hermitian) ⊗ I_8 and
//   out = ( Σ_{a,b} ReO[a][b] * dot(x[8a..], x[8b..]) ) / ||x||^2.
// Kernel A builds ReO (8x8); kernel B stages 128-row tiles through shared
// memory (coalesced HBM loads, conflict-free padded smem reads) and does the
// per-row Gram quadratic form.
// ---------------------------------------------------------------------------

__device__ float g_C[64];   // ReO, row-major 8x8

struct c2 { float x, y; };
__device__ __forceinline__ c2 cmul(c2 a, c2 b) { return { a.x*b.x - a.y*b.y, a.x*b.y + a.y*b.x }; }
__device__ __forceinline__ c2 cadd(c2 a, c2 b) { return { a.x + b.x, a.y + b.y }; }

struct U2 { c2 m00, m01, m10, m11; };

// qiskit U(theta, phi, lam)
__device__ __forceinline__ U2 u3(float th, float ph, float la) {
    float s, c;   sincosf(0.5f * th, &s, &c);
    float sph, cph; sincosf(ph, &sph, &cph);
    float sla, cla; sincosf(la, &sla, &cla);
    float spl, cpl; sincosf(ph + la, &spl, &cpl);
    U2 u;
    u.m00 = {  c,        0.f     };
    u.m01 = { -cla * s, -sla * s };
    u.m10 = {  cph * s,  sph * s };
    u.m11 = {  cpl * c,  spl * c };
    return u;
}

template <int BIT>
__device__ __forceinline__ void apply1(c2 (&w)[8], U2 u) {
#pragma unroll
    for (int a = 0; a < 8; a++) {
        if (!(a & BIT)) {
            c2 t0 = w[a], t1 = w[a | BIT];
            w[a]       = cadd(cmul(u.m00, t0), cmul(u.m01, t1));
            w[a | BIT] = cadd(cmul(u.m10, t0), cmul(u.m11, t1));
        }
    }
}

// Build ReO. 3-qubit index a: bit0 = qubit3, bit1 = qubit4, bit2 = qubit5.
// Sub-circuit (forward): U3(q3;9), U3(q4;12), U3(q5;15), CX(4->3), P(19;q3),
// U3(q3;26), U3(q5;29), CU(35;3->5). O = W† diag(z) W, z_a = +1 iff (a&4)==0.
__global__ void build_obs_kernel(const float* __restrict__ p) {
    __shared__ float Wr[8][8];
    __shared__ float Wi[8][8];
    int t = threadIdx.x;

    if (t < 8) {
        c2 w[8];
#pragma unroll
        for (int a = 0; a < 8; a++) w[a] = { (a == t) ? 1.f : 0.f, 0.f };

        apply1<1>(w, u3(p[9],  p[10], p[11]));   // layer1 q3
        apply1<2>(w, u3(p[12], p[13], p[14]));   // layer1 q4
        apply1<4>(w, u3(p[15], p[16], p[17]));   // layer1 q5

        // CX control q4 (bit1) -> target q3 (bit0)
#pragma unroll
        for (int a = 0; a < 8; a++) {
            if ((a & 2) && !(a & 1)) { c2 tmp = w[a]; w[a] = w[a | 1]; w[a | 1] = tmp; }
        }

        // P(params[19]) on q3 (bit0)
        {
            float sp, cp; sincosf(p[19], &sp, &cp);
            c2 e = { cp, sp };
#pragma unroll
            for (int a = 0; a < 8; a++) if (a & 1) w[a] = cmul(w[a], e);
        }

        apply1<1>(w, u3(p[26], p[27], p[28]));   // layer2 q3
        apply1<4>(w, u3(p[29], p[30], p[31]));   // layer2 q5

        // CU(params 35..37): control q3 (bit0) -> target q5 (bit2)
        {
            U2 u = u3(p[35], p[36], p[37]);
#pragma unroll
            for (int a = 0; a < 8; a++) {
                if ((a & 1) && !(a & 4)) {
                    c2 t0 = w[a], t1 = w[a | 4];
                    w[a]     = cadd(cmul(u.m00, t0), cmul(u.m01, t1));
                    w[a | 4] = cadd(cmul(u.m10, t0), cmul(u.m11, t1));
                }
            }
        }

#pragma unroll
        for (int a = 0; a < 8; a++) { Wr[a][t] = w[a].x; Wi[a][t] = w[a].y; }
    }
    __syncthreads();

    if (t < 64) {
        int a = t >> 3, b = t & 7;
        float acc = 0.f;
#pragma unroll
        for (int c = 0; c < 8; c++) {
            float z = (c & 4) ? -1.f : 1.f;
            acc += z * (Wr[c][a] * Wr[c][b] + Wi[c][a] * Wi[c][b]);
        }
        g_C[t] = acc;
    }
}

// 128 rows per block. Coalesced gmem->smem staging (padded to 68 floats/row:
// STS.128 and row-wise LDS.128 are bank-conflict-free per 8-lane phase), then
// one row per thread: Gram quadratic form against ReO, normalized by ||x||^2.
static constexpr int TPB = 128;
static constexpr int ROW_PAD = 68;   // 64 + 4 floats

__global__ void __launch_bounds__(TPB) quadform_kernel(
    const float* __restrict__ feat, float* __restrict__ out, int n) {
    __shared__ float tile[TPB * ROW_PAD];
    __shared__ float C[64];
    int tid = threadIdx.x;
    if (tid < 64) {
        int a = tid >> 3, b = tid & 7;
        float v = g_C[tid];
        C[tid] = (a == b) ? v : 2.f * v;   // off-diagonals counted twice
    }

    int base = blockIdx.x * TPB;
    int rows = min(TPB, n - base);
    int nvec = rows * 16;                  // float4s to stage
    const float4* src = reinterpret_cast<const float4*>(feat) + (size_t)base * 16;
    for (int v = tid; v < nvec; v += TPB) {
        float4 d = __ldg(src + v);
        int r = v >> 4, c4 = v & 15;
        *reinterpret_cast<float4*>(&tile[r * ROW_PAD + c4 * 4]) = d;
    }
    __syncthreads();

    int row = base + tid;
    if (row >= n) return;

    float x[64];
    const float* rp = &tile[tid * ROW_PAD];
#pragma unroll
    for (int i = 0; i < 16; i++) {
        float4 v = *reinterpret_cast<const float4*>(rp + i * 4);
        x[4*i + 0] = v.x; x[4*i + 1] = v.y; x[4*i + 2] = v.z; x[4*i + 3] = v.w;
    }

    float Q = 0.f, N = 0.f;
#pragma unroll
    for (int a = 0; a < 8; a++) {
#pragma unroll
        for (int b = a; b < 8; b++) {
            float s = 0.f;
#pragma unroll
            for (int k = 0; k < 8; k++) s += x[8*a + k] * x[8*b + k];
            Q += C[8*a + b] * s;
            if (a == b) N += s;
        }
    }

    // jnp.isclose(norm, 0) with atol=1e-8 -> N = norm^2 <= 1e-16 -> psi = e0
    out[row] = (N <= 1e-16f) ? C[0] : (Q / N);
}

extern "C" void kernel_launch(void* const* d_in, const int* in_sizes, int n_in,
                              void* d_out, int out_size) {
    // metadata order: features (B*64 floats), params (54 floats). Be defensive
    // about ordering by size.
    int fi = 0, pi = 1;
    if (n_in >= 2 && in_sizes[0] == 54) { fi = 1; pi = 0; }

    const float* feat   = (const float*)d_in[fi];
    const float* params = (const float*)d_in[pi];
    float* out = (float*)d_out;

    int n = in_sizes[fi] / 64;

    build_obs_kernel<<<1, 64>>>(params);
    int grid = (n + TPB - 1) / TPB;
    quadform_kernel<<<grid, TPB>>>(feat, out, n);
}

// round 3
// speedup vs baseline: 1.6212x; 1.1345x over previous
#include <cuda_runtime.h>
#include <cuda_pipeline.h>

// ---------------------------------------------------------------------------
// QuantumLayer: out[r] = <psi_r| U† Z5 U |psi_r>, psi_r = x_r / ||x_r||.
// Lightcone of Z5 touches only qubits {3,4,5} (top 3 index bits), so
// M = O (8x8 Hermitian) ⊗ I_8 and
//   out = ( Σ_{a,b} ReO[a][b] * dot(x[8a..], x[8b..]) ) / ||x||^2.
// Single persistent kernel: each block rebuilds ReO (cheap, overlapped with
// the first cp.async tile), then grid-strides over 64-row tiles with 2-stage
// cp.async double buffering so the DRAM pipe never drains.
// ---------------------------------------------------------------------------

struct c2 { float x, y; };
__device__ __forceinline__ c2 cmul(c2 a, c2 b) { return { a.x*b.x - a.y*b.y, a.x*b.y + a.y*b.x }; }
__device__ __forceinline__ c2 cadd(c2 a, c2 b) { return { a.x + b.x, a.y + b.y }; }

struct U2 { c2 m00, m01, m10, m11; };

// qiskit U(theta, phi, lam)
__device__ __forceinline__ U2 u3(float th, float ph, float la) {
    float s, c;   sincosf(0.5f * th, &s, &c);
    float sph, cph; sincosf(ph, &sph, &cph);
    float sla, cla; sincosf(la, &sla, &cla);
    float spl, cpl; sincosf(ph + la, &spl, &cpl);
    U2 u;
    u.m00 = {  c,        0.f     };
    u.m01 = { -cla * s, -sla * s };
    u.m10 = {  cph * s,  sph * s };
    u.m11 = {  cpl * c,  spl * c };
    return u;
}

template <int BIT>
__device__ __forceinline__ void apply1(c2 (&w)[8], U2 u) {
#pragma unroll
    for (int a = 0; a < 8; a++) {
        if (!(a & BIT)) {
            c2 t0 = w[a], t1 = w[a | BIT];
            w[a]       = cadd(cmul(u.m00, t0), cmul(u.m01, t1));
            w[a | BIT] = cadd(cmul(u.m10, t0), cmul(u.m11, t1));
        }
    }
}

static constexpr int TPB = 64;       // threads = rows per tile
static constexpr int ROW_PAD = 68;   // 64 + 4 floats: LDS.128 conflict-free
static constexpr int TILE_FLOATS = TPB * ROW_PAD;

__global__ void __launch_bounds__(TPB) quadform_kernel(
    const float* __restrict__ feat, const float* __restrict__ p,
    float* __restrict__ out, int n, int ntiles) {
    __shared__ float tile[2][TILE_FLOATS];
    __shared__ float C[64];
    __shared__ float Wr[8][8];
    __shared__ float Wi[8][8];
    int tid = threadIdx.x;

    // ---- kick off prefetch of this block's first tile immediately ----
    auto prefetch = [&](int tt, int buf) {
        int base = tt * TPB;
        int rows = min(TPB, n - base);
        int nvec = rows * 16;
        const float4* src = reinterpret_cast<const float4*>(feat) + (size_t)base * 16;
#pragma unroll 4
        for (int v = tid; v < nvec; v += TPB) {
            int r = v >> 4, c4 = v & 15;
            __pipeline_memcpy_async(&tile[buf][r * ROW_PAD + c4 * 4], src + v, 16);
        }
    };

    int t0 = blockIdx.x;
    if (t0 < ntiles) prefetch(t0, 0);
    __pipeline_commit();   // group #0

    // ---- build ReO while the first tile streams in ----
    // 3-qubit index a: bit0=q3, bit1=q4, bit2=q5. Sub-circuit (forward):
    // U3(q3;9), U3(q4;12), U3(q5;15), CX(4->3), P(19;q3), U3(q3;26),
    // U3(q5;29), CU(35;3->5). O = W† diag(z) W, z_a = +1 iff (a&4)==0.
    if (tid < 8) {
        c2 w[8];
#pragma unroll
        for (int a = 0; a < 8; a++) w[a] = { (a == tid) ? 1.f : 0.f, 0.f };

        apply1<1>(w, u3(p[9],  p[10], p[11]));
        apply1<2>(w, u3(p[12], p[13], p[14]));
        apply1<4>(w, u3(p[15], p[16], p[17]));

        // CX control q4 (bit1) -> target q3 (bit0)
#pragma unroll
        for (int a = 0; a < 8; a++)
            if ((a & 2) && !(a & 1)) { c2 tmp = w[a]; w[a] = w[a | 1]; w[a | 1] = tmp; }

        // P(params[19]) on q3 (bit0)
        {
            float sp, cp; sincosf(p[19], &sp, &cp);
            c2 e = { cp, sp };
#pragma unroll
            for (int a = 0; a < 8; a++) if (a & 1) w[a] = cmul(w[a], e);
        }

        apply1<1>(w, u3(p[26], p[27], p[28]));
        apply1<4>(w, u3(p[29], p[30], p[31]));

        // CU(params 35..37): control q3 (bit0) -> target q5 (bit2)
        {
            U2 u = u3(p[35], p[36], p[37]);
#pragma unroll
            for (int a = 0; a < 8; a++) {
                if ((a & 1) && !(a & 4)) {
                    c2 t0c = w[a], t1c = w[a | 4];
                    w[a]     = cadd(cmul(u.m00, t0c), cmul(u.m01, t1c));
                    w[a | 4] = cadd(cmul(u.m10, t0c), cmul(u.m11, t1c));
                }
            }
        }

#pragma unroll
        for (int a = 0; a < 8; a++) { Wr[a][tid] = w[a].x; Wi[a][tid] = w[a].y; }
    }
    __syncthreads();
    {
        int a = tid >> 3, b = tid & 7;
        float acc = 0.f;
#pragma unroll
        for (int c = 0; c < 8; c++) {
            float z = (c & 4) ? -1.f : 1.f;
            acc += z * (Wr[c][a] * Wr[c][b] + Wi[c][a] * Wi[c][b]);
        }
        C[tid] = (a == b) ? acc : 2.f * acc;   // off-diagonals counted twice
    }

    // ---- pipelined grid-stride main loop ----
    int buf = 0;
    for (int tt = t0; tt < ntiles; tt += gridDim.x) {
        int nxt = tt + gridDim.x;
        if (nxt < ntiles) prefetch(nxt, buf ^ 1);
        __pipeline_commit();          // unconditional: keeps group counting uniform
        __pipeline_wait_prior(1);     // current tile's group complete
        __syncthreads();              // data + C visible to all threads

        int row = tt * TPB + tid;
        if (row < n) {
            float x[64];
            const float* rp = &tile[buf][tid * ROW_PAD];
#pragma unroll
            for (int i = 0; i < 16; i++) {
                float4 v = *reinterpret_cast<const float4*>(rp + i * 4);
                x[4*i + 0] = v.x; x[4*i + 1] = v.y; x[4*i + 2] = v.z; x[4*i + 3] = v.w;
            }

            float Q = 0.f, N = 0.f;
#pragma unroll
            for (int a = 0; a < 8; a++) {
#pragma unroll
                for (int b = a; b < 8; b++) {
                    float s = 0.f;
#pragma unroll
                    for (int k = 0; k < 8; k++) s += x[8*a + k] * x[8*b + k];
                    Q += C[8*a + b] * s;
                    if (a == b) N += s;
                }
            }
            // jnp.isclose(norm,0), atol=1e-8 -> N <= 1e-16 -> psi = e0
            out[row] = (N <= 1e-16f) ? C[0] : (Q / N);
        }
        __syncthreads();              // all done reading buf before it is refilled
        buf ^= 1;
    }
}

extern "C" void kernel_launch(void* const* d_in, const int* in_sizes, int n_in,
                              void* d_out, int out_size) {
    // metadata order: features (B*64 floats), params (54 floats); be defensive.
    int fi = 0, pi = 1;
    if (n_in >= 2 && in_sizes[0] == 54) { fi = 1; pi = 0; }

    const float* feat   = (const float*)d_in[fi];
    const float* params = (const float*)d_in[pi];
    float* out = (float*)d_out;

    int n = in_sizes[fi] / 64;
    int ntiles = (n + TPB - 1) / TPB;

    // 6 blocks/SM (2x17.4KB smem) x 148 SMs
    int grid = 148 * 6;
    if (grid > ntiles) grid = ntiles;

    quadform_kernel<<<grid, TPB>>>(feat, params, out, n, ntiles);
}